// round 12
// baseline (speedup 1.0000x reference)
#include <cuda_runtime.h>
#include <cuda_fp16.h>

#define NMAX 200000
#define EMAX 6400000
#define HD 128

// ---------------- mma / ldmatrix helpers ------------------------------------
__device__ __forceinline__ unsigned smem_u32(const void* p) {
    return (unsigned)__cvta_generic_to_shared(p);
}
__device__ __forceinline__ void ldsm_x4(unsigned& r0, unsigned& r1, unsigned& r2, unsigned& r3,
                                        unsigned addr) {
    asm volatile("ldmatrix.sync.aligned.m8n8.x4.shared.b16 {%0,%1,%2,%3}, [%4];"
                 : "=r"(r0), "=r"(r1), "=r"(r2), "=r"(r3) : "r"(addr));
}
__device__ __forceinline__ void ldsm_x4_trans(unsigned& r0, unsigned& r1, unsigned& r2, unsigned& r3,
                                              unsigned addr) {
    asm volatile("ldmatrix.sync.aligned.m8n8.x4.trans.shared.b16 {%0,%1,%2,%3}, [%4];"
                 : "=r"(r0), "=r"(r1), "=r"(r2), "=r"(r3) : "r"(addr));
}
__device__ __forceinline__ void mma16816(float* d, unsigned a0, unsigned a1, unsigned a2, unsigned a3,
                                         unsigned b0, unsigned b1) {
    asm volatile("mma.sync.aligned.m16n8k16.row.col.f32.f16.f16.f32 "
                 "{%0,%1,%2,%3}, {%4,%5,%6,%7}, {%8,%9}, {%0,%1,%2,%3};"
                 : "+f"(d[0]), "+f"(d[1]), "+f"(d[2]), "+f"(d[3])
                 : "r"(a0), "r"(a1), "r"(a2), "r"(a3), "r"(b0), "r"(b1));
}

// ---------------- static device scratch (no allocations allowed) ------------
__device__ int g_cnt[NMAX];
__device__ int g_rowptr[NMAX + 1];
__device__ int g_cur[NMAX];
__device__ int g_part[256];
__device__ int g_partoff[256];
__device__ __align__(16) uint2 g_edges[EMAX];                 // (col, val-bits)
__device__ __align__(16) __half g_neighh[(size_t)NMAX * HD];  // fp16 neighbor agg
__device__ __align__(16) __half g_hb[(size_t)NMAX * HD];      // fp16 h shadow gen-0 (MLP)
__device__ __align__(16) __half g_hb2[(size_t)NMAX * HD];     // fp16 h shadow gen-1 (layer0)
__device__ __align__(16) __half g_w1h[64 * 128];              // padded W1 fp16
__device__ __align__(16) __half g_w2h[128 * 128];
__device__ __align__(16) __half g_wlh[2 * 256 * 128];         // [l][Ws;Wn][128]
__device__ float g_gsum[HD];
__device__ unsigned g_gmax[HD];

// ---------------- weight fp16 pre-conversion --------------------------------
__global__ void k_prep(const float* __restrict__ W1, const float* __restrict__ W2,
                       const float* __restrict__ Wself, const float* __restrict__ Wneigh) {
    int i = blockIdx.x * blockDim.x + threadIdx.x;
    if (i < 64 * 128) {
        int r = i >> 7, c = i & 127;
        g_w1h[i] = __float2half(r < 60 ? W1[r * 128 + c] : 0.f);
    } else if (i < 64 * 128 + 128 * 128) {
        int j = i - 64 * 128;
        g_w2h[j] = __float2half(W2[j]);
    } else if (i < 64 * 128 + 128 * 128 + 2 * 256 * 128) {
        int j = i - 64 * 128 - 128 * 128;
        int l = j >> 15;
        int r = (j & 32767) >> 7;
        int c = j & 127;
        float v = (r < 128) ? Wself[l * 16384 + r * 128 + c]
                            : Wneigh[l * 16384 + (r - 128) * 128 + c];
        g_wlh[j] = __float2half(v);
    }
}

// ---------------- CSR build: histogram -> parallel scan -> reorder ----------
__global__ void k_hist(const int* __restrict__ er, int e) {
    int i = blockIdx.x * blockDim.x + threadIdx.x;
    int i4 = i * 4;
    if (i4 + 3 < e) {
        int4 r = *(const int4*)&er[i4];
        atomicAdd(&g_cnt[r.x], 1);
        atomicAdd(&g_cnt[r.y], 1);
        atomicAdd(&g_cnt[r.z], 1);
        atomicAdd(&g_cnt[r.w], 1);
    } else {
        for (int j = i4; j < e; j++) atomicAdd(&g_cnt[er[j]], 1);
    }
}

__global__ void k_scanA(int n) {
    __shared__ int s[256];
    int b = blockIdx.x, t = threadIdx.x;
    int i0 = b * 1024 + t * 4;
    int sum = 0;
    #pragma unroll
    for (int j = 0; j < 4; j++) { int i = i0 + j; if (i < n) sum += g_cnt[i]; }
    s[t] = sum;
    __syncthreads();
    for (int off = 128; off > 0; off >>= 1) {
        if (t < off) s[t] += s[t + off];
        __syncthreads();
    }
    if (t == 0) g_part[b] = s[0];
}

__global__ void k_scanB(int nb, int n) {
    __shared__ int s[256];
    int t = threadIdx.x;
    if (t < HD) { g_gsum[t] = 0.f; g_gmax[t] = 0u; }
    int v = (t < nb) ? g_part[t] : 0;
    s[t] = v;
    __syncthreads();
    for (int off = 1; off < 256; off <<= 1) {
        int u = (t >= off) ? s[t - off] : 0;
        __syncthreads();
        s[t] += u;
        __syncthreads();
    }
    if (t < nb) g_partoff[t] = s[t] - v;
    if (t == 255) g_rowptr[n] = s[255];
}

__global__ void k_scanC(int n) {
    __shared__ int s[256];
    int b = blockIdx.x, t = threadIdx.x;
    int i0 = b * 1024 + t * 4;
    int c[4]; int sum = 0;
    #pragma unroll
    for (int j = 0; j < 4; j++) { int i = i0 + j; c[j] = (i < n) ? g_cnt[i] : 0; sum += c[j]; }
    s[t] = sum;
    __syncthreads();
    for (int off = 1; off < 256; off <<= 1) {
        int u = (t >= off) ? s[t - off] : 0;
        __syncthreads();
        s[t] += u;
        __syncthreads();
    }
    int pre = g_partoff[b] + s[t] - sum;
    #pragma unroll
    for (int j = 0; j < 4; j++) {
        int i = i0 + j;
        if (i < n) { g_rowptr[i] = pre; g_cur[i] = pre; pre += c[j]; }
    }
}

__global__ void k_reorder(const int* __restrict__ er, const int* __restrict__ ec,
                          const float* __restrict__ ev, int e) {
    int i = blockIdx.x * blockDim.x + threadIdx.x;
    int i4 = i * 4;
    if (i4 + 3 < e) {
        int4 r = *(const int4*)&er[i4];
        int4 c = *(const int4*)&ec[i4];
        float4 v = *(const float4*)&ev[i4];
        int p0 = atomicAdd(&g_cur[r.x], 1);
        int p1 = atomicAdd(&g_cur[r.y], 1);
        int p2 = atomicAdd(&g_cur[r.z], 1);
        int p3 = atomicAdd(&g_cur[r.w], 1);
        g_edges[p0] = make_uint2((unsigned)c.x, __float_as_uint(v.x));
        g_edges[p1] = make_uint2((unsigned)c.y, __float_as_uint(v.y));
        g_edges[p2] = make_uint2((unsigned)c.z, __float_as_uint(v.z));
        g_edges[p3] = make_uint2((unsigned)c.w, __float_as_uint(v.w));
    } else {
        for (int j = i4; j < e; j++) {
            int p = atomicAdd(&g_cur[er[j]], 1);
            g_edges[p] = make_uint2((unsigned)ec[j], __float_as_uint(ev[j]));
        }
    }
}

// ---------------- tensor-core input MLP -------------------------------------
#define XSTR 72
#define WSTR 136
#define SMEM_MLP_TC ((128 * XSTR + 64 * WSTR + 128 * WSTR + 128 * WSTR) * 2)

__global__ void __launch_bounds__(256, 1) k_mlp_tc(
    const int* __restrict__ mi, const int* __restrict__ wi, const int* __restrict__ ti,
    const float* __restrict__ cont,
    const float* __restrict__ memb, const float* __restrict__ wemb, const float* __restrict__ temb,
    const float* __restrict__ b1, const float* __restrict__ b2,
    float* __restrict__ hout, int n)
{
    extern __shared__ __half smh[];
    __half* sX  = smh;
    __half* sW1 = sX + 128 * XSTR;
    __half* sW2 = sW1 + 64 * WSTR;
    __half* sH1 = sW2 + 128 * WSTR;

    int tid = threadIdx.x;
    int base = blockIdx.x * 128;

    for (int i = tid; i < 64 * 16; i += 256) {
        int r = i >> 4, q = i & 15;
        *(uint4*)&sW1[r * WSTR + q * 8] = *(const uint4*)&g_w1h[i * 8];
    }
    for (int i = tid; i < 128 * 16; i += 256) {
        int r = i >> 4, q = i & 15;
        *(uint4*)&sW2[r * WSTR + q * 8] = *(const uint4*)&g_w2h[i * 8];
    }
    for (int i = tid; i < 128 * 64; i += 256) {
        int nd = i >> 6, f = i & 63;
        int node = base + nd;
        float v = 0.f;
        if (node < n && f < 60) {
            if (f < 16)       v = memb[mi[node] * 16 + f];
            else if (f < 32)  v = wemb[wi[node] * 16 + (f - 16)];
            else if (f < 48)  v = temb[ti[node] * 16 + (f - 32)];
            else              v = cont[(size_t)node * 12 + (f - 48)];
        }
        sX[nd * XSTR + f] = __float2half(v);
    }
    __syncthreads();

    int wid = tid >> 5;
    int lane = tid & 31;
    int m0 = wid * 16;
    int lg = lane >> 3, lr = lane & 7;
    int a_row = m0 + lr + (lg & 1) * 8;
    int a_colb = (lg >> 1) * 8;
    int b_rowb = lr + (lg & 1) * 8;
    int b_colb = (lg >> 1) * 8;
    int row0 = m0 + (lane >> 2);
    int cbase = (lane & 3) * 2;

    unsigned sX_b = smem_u32(sX);
    unsigned sW1_b = smem_u32(sW1);
    unsigned sW2_b = smem_u32(sW2);
    unsigned sH1_b = smem_u32(sH1);

    float acc[16][4];
    #pragma unroll
    for (int t = 0; t < 16; t++)
        #pragma unroll
        for (int c = 0; c < 4; c++) acc[t][c] = 0.f;

    #pragma unroll
    for (int ks = 0; ks < 4; ks++) {
        int k0 = ks * 16;
        unsigned a0, a1, a2, a3;
        ldsm_x4(a0, a1, a2, a3, sX_b + (unsigned)(a_row * XSTR + k0 + a_colb) * 2u);
        #pragma unroll
        for (int j = 0; j < 8; j++) {
            unsigned b0, b1r, b2r, b3;
            ldsm_x4_trans(b0, b1r, b2r, b3,
                          sW1_b + (unsigned)((k0 + b_rowb) * WSTR + j * 16 + b_colb) * 2u);
            mma16816(acc[2 * j], a0, a1, a2, a3, b0, b1r);
            mma16816(acc[2 * j + 1], a0, a1, a2, a3, b2r, b3);
        }
    }
    #pragma unroll
    for (int t = 0; t < 16; t++) {
        int col = t * 8 + cbase;
        float bb0 = b1[col], bb1 = b1[col + 1];
        __half2 h0 = __floats2half2_rn(fmaxf(acc[t][0] + bb0, 0.f), fmaxf(acc[t][1] + bb1, 0.f));
        __half2 h1v = __floats2half2_rn(fmaxf(acc[t][2] + bb0, 0.f), fmaxf(acc[t][3] + bb1, 0.f));
        *(__half2*)&sH1[row0 * WSTR + col] = h0;
        *(__half2*)&sH1[(row0 + 8) * WSTR + col] = h1v;
    }
    __syncthreads();

    #pragma unroll
    for (int t = 0; t < 16; t++)
        #pragma unroll
        for (int c = 0; c < 4; c++) acc[t][c] = 0.f;

    #pragma unroll 1
    for (int ks = 0; ks < 8; ks++) {
        int k0 = ks * 16;
        unsigned a0, a1, a2, a3;
        ldsm_x4(a0, a1, a2, a3, sH1_b + (unsigned)(a_row * WSTR + k0 + a_colb) * 2u);
        #pragma unroll
        for (int j = 0; j < 8; j++) {
            unsigned b0, b1r, b2r, b3;
            ldsm_x4_trans(b0, b1r, b2r, b3,
                          sW2_b + (unsigned)((k0 + b_rowb) * WSTR + j * 16 + b_colb) * 2u);
            mma16816(acc[2 * j], a0, a1, a2, a3, b0, b1r);
            mma16816(acc[2 * j + 1], a0, a1, a2, a3, b2r, b3);
        }
    }
    int node0 = base + row0;
    int node1 = node0 + 8;
    #pragma unroll
    for (int t = 0; t < 16; t++) {
        int col = t * 8 + cbase;
        float bb0 = b2[col], bb1 = b2[col + 1];
        if (node0 < n) {
            float x = fmaxf(acc[t][0] + bb0, 0.f);
            float y = fmaxf(acc[t][1] + bb1, 0.f);
            size_t off = (size_t)node0 * 128 + col;
            *(float2*)&hout[off] = make_float2(x, y);
            *(__half2*)&g_hb[off] = __floats2half2_rn(x, y);
        }
        if (node1 < n) {
            float x = fmaxf(acc[t][2] + bb0, 0.f);
            float y = fmaxf(acc[t][3] + bb1, 0.f);
            size_t off = (size_t)node1 * 128 + col;
            *(float2*)&hout[off] = make_float2(x, y);
            *(__half2*)&g_hb[off] = __floats2half2_rn(x, y);
        }
    }
}

// ---------------- SpMM: half-warp per row, fp16 in, fp16 out (R6 proven) ----
__global__ void k_spmm(const __half* __restrict__ hb, int row0c, int rowEnd) {
    int row = row0c + ((blockIdx.x * blockDim.x + threadIdx.x) >> 4);
    if (row >= rowEnd) return;
    int s = threadIdx.x & 15;
    int beg = g_rowptr[row], end = g_rowptr[row + 1];
    float acc0 = 0.f, acc1 = 0.f, acc2 = 0.f, acc3 = 0.f;
    float acc4 = 0.f, acc5 = 0.f, acc6 = 0.f, acc7 = 0.f;
    int e = beg;
    for (; e + 1 < end; e += 2) {
        uint2 e0 = __ldcs(&g_edges[e]);
        uint2 e1 = __ldcs(&g_edges[e + 1]);
        float v0 = __uint_as_float(e0.y);
        float v1 = __uint_as_float(e1.y);
        uint4 x0 = *(const uint4*)&hb[(size_t)e0.x * 128 + s * 8];
        uint4 x1 = *(const uint4*)&hb[(size_t)e1.x * 128 + s * 8];
        float2 p;
        p = __half22float2(*(__half2*)&x0.x); acc0 += v0 * p.x; acc1 += v0 * p.y;
        p = __half22float2(*(__half2*)&x0.y); acc2 += v0 * p.x; acc3 += v0 * p.y;
        p = __half22float2(*(__half2*)&x0.z); acc4 += v0 * p.x; acc5 += v0 * p.y;
        p = __half22float2(*(__half2*)&x0.w); acc6 += v0 * p.x; acc7 += v0 * p.y;
        p = __half22float2(*(__half2*)&x1.x); acc0 += v1 * p.x; acc1 += v1 * p.y;
        p = __half22float2(*(__half2*)&x1.y); acc2 += v1 * p.x; acc3 += v1 * p.y;
        p = __half22float2(*(__half2*)&x1.z); acc4 += v1 * p.x; acc5 += v1 * p.y;
        p = __half22float2(*(__half2*)&x1.w); acc6 += v1 * p.x; acc7 += v1 * p.y;
    }
    if (e < end) {
        uint2 e0 = __ldcs(&g_edges[e]);
        float v0 = __uint_as_float(e0.y);
        uint4 x0 = *(const uint4*)&hb[(size_t)e0.x * 128 + s * 8];
        float2 p;
        p = __half22float2(*(__half2*)&x0.x); acc0 += v0 * p.x; acc1 += v0 * p.y;
        p = __half22float2(*(__half2*)&x0.y); acc2 += v0 * p.x; acc3 += v0 * p.y;
        p = __half22float2(*(__half2*)&x0.z); acc4 += v0 * p.x; acc5 += v0 * p.y;
        p = __half22float2(*(__half2*)&x0.w); acc6 += v0 * p.x; acc7 += v0 * p.y;
    }
    uint4 o;
    __half2 h0 = __floats2half2_rn(acc0, acc1);
    __half2 h1 = __floats2half2_rn(acc2, acc3);
    __half2 h2 = __floats2half2_rn(acc4, acc5);
    __half2 h3 = __floats2half2_rn(acc6, acc7);
    o.x = *(unsigned*)&h0; o.y = *(unsigned*)&h1;
    o.z = *(unsigned*)&h2; o.w = *(unsigned*)&h3;
    __stcs((uint4*)&g_neighh[(size_t)row * 128 + s * 8], o);
}

// ---------------- tensor-core layer (+ shuffle-fused global pool) -----------
#define ASTR 264
#define SMEM_TC ((256 * WSTR + 128 * ASTR) * 2)

__global__ void __launch_bounds__(256, 1) k_layer_tc(
    const __half* __restrict__ wl, const float* __restrict__ bs, const float* __restrict__ bn,
    float* __restrict__ h, const __half* __restrict__ hb_in, __half* __restrict__ hb_out,
    int base0, int n, int write_hb, int do_pool)
{
    extern __shared__ __half smh[];
    __half* sW = smh;
    __half* sA = smh + 256 * WSTR;
    __shared__ float psum[8][HD];
    __shared__ unsigned pmax[8][HD];

    int tid = threadIdx.x;
    int base = base0 + blockIdx.x * 128;

    for (int i = tid; i < 256 * 16; i += 256) {
        int r = i >> 4, q = i & 15;
        *(uint4*)&sW[r * WSTR + q * 8] = *(const uint4*)&wl[i * 8];
    }
    for (int i = tid; i < 128 * 32; i += 256) {
        int nd = i >> 5, q = i & 31;
        int node = base + nd;
        uint4 v = {0u, 0u, 0u, 0u};
        if (node < n) {
            if (q < 16) v = *(const uint4*)&hb_in[(size_t)node * 128 + q * 8];
            else        v = *(const uint4*)&g_neighh[(size_t)node * 128 + (q - 16) * 8];
        }
        *(uint4*)&sA[nd * ASTR + q * 8] = v;
    }
    __syncthreads();

    int wid = tid >> 5;
    int lane = tid & 31;
    int m0 = wid * 16;
    int lg = lane >> 3, lr = lane & 7;
    int a_row = m0 + lr + (lg & 1) * 8;
    int a_colb = (lg >> 1) * 8;
    int b_rowb = lr + (lg & 1) * 8;
    int b_colb = (lg >> 1) * 8;

    unsigned sA_b = smem_u32(sA);
    unsigned sW_b = smem_u32(sW);

    float acc[16][4];
    #pragma unroll
    for (int t = 0; t < 16; t++)
        #pragma unroll
        for (int c = 0; c < 4; c++) acc[t][c] = 0.f;

    #pragma unroll 1
    for (int ks = 0; ks < 16; ks++) {
        int k0 = ks * 16;
        unsigned a0, a1, a2, a3;
        ldsm_x4(a0, a1, a2, a3, sA_b + (unsigned)(a_row * ASTR + k0 + a_colb) * 2u);
        #pragma unroll
        for (int j = 0; j < 8; j++) {
            unsigned b0, b1, b2, b3;
            ldsm_x4_trans(b0, b1, b2, b3,
                          sW_b + (unsigned)((k0 + b_rowb) * WSTR + j * 16 + b_colb) * 2u);
            mma16816(acc[2 * j], a0, a1, a2, a3, b0, b1);
            mma16816(acc[2 * j + 1], a0, a1, a2, a3, b2, b3);
        }
    }

    int row0 = m0 + (lane >> 2);
    int cbase = (lane & 3) * 2;
    int node0 = base + row0;
    int node1 = node0 + 8;
    #pragma unroll
    for (int t = 0; t < 16; t++) {
        int col = t * 8 + cbase;
        float bsum0 = bs[col] + bn[col];
        float bsum1 = bs[col + 1] + bn[col + 1];
        float s0 = 0.f, s1 = 0.f, m0v = 0.f, m1v = 0.f;
        if (node0 < n) {
            size_t off = (size_t)node0 * 128 + col;
            float2* p = (float2*)&h[off];
            float2 hv = *p;
            hv.x += fmaxf(acc[t][0] + bsum0, 0.f);
            hv.y += fmaxf(acc[t][1] + bsum1, 0.f);
            *p = hv;
            if (write_hb) *(__half2*)&hb_out[off] = __floats2half2_rn(hv.x, hv.y);
            s0 += hv.x; s1 += hv.y;
            m0v = fmaxf(m0v, hv.x); m1v = fmaxf(m1v, hv.y);
        }
        if (node1 < n) {
            size_t off = (size_t)node1 * 128 + col;
            float2* p = (float2*)&h[off];
            float2 hv = *p;
            hv.x += fmaxf(acc[t][2] + bsum0, 0.f);
            hv.y += fmaxf(acc[t][3] + bsum1, 0.f);
            *p = hv;
            if (write_hb) *(__half2*)&hb_out[off] = __floats2half2_rn(hv.x, hv.y);
            s0 += hv.x; s1 += hv.y;
            m0v = fmaxf(m0v, hv.x); m1v = fmaxf(m1v, hv.y);
        }
        if (do_pool) {
            #pragma unroll
            for (int o = 16; o >= 4; o >>= 1) {
                s0 += __shfl_down_sync(0xffffffffu, s0, o);
                s1 += __shfl_down_sync(0xffffffffu, s1, o);
                m0v = fmaxf(m0v, __shfl_down_sync(0xffffffffu, m0v, o));
                m1v = fmaxf(m1v, __shfl_down_sync(0xffffffffu, m1v, o));
            }
            if (lane < 4) {
                psum[wid][col] = s0;
                psum[wid][col + 1] = s1;
                pmax[wid][col] = __float_as_uint(m0v);
                pmax[wid][col + 1] = __float_as_uint(m1v);
            }
        }
    }
    if (do_pool) {
        __syncthreads();
        if (tid < HD) {
            float s = 0.f;
            unsigned m = 0u;
            #pragma unroll
            for (int w = 0; w < 8; w++) {
                s += psum[w][tid];
                m = max(m, pmax[w][tid]);
            }
            atomicAdd(&g_gsum[tid], s);
            atomicMax(&g_gmax[tid], m);
        }
    }
}

// ---------------- final: write pooled output --------------------------------
__global__ void k_final(float* __restrict__ out, int n) {
    int t = threadIdx.x;  // 256
    if (t < 128) out[t] = g_gsum[t] / (float)n;
    else out[t] = __uint_as_float(g_gmax[t - 128]);
}

// ---------------- launch -----------------------------------------------------
extern "C" void kernel_launch(void* const* d_in, const int* in_sizes, int n_in,
                              void* d_out, int out_size) {
    const int*   mi   = (const int*)d_in[0];
    const int*   wi   = (const int*)d_in[1];
    const int*   ti   = (const int*)d_in[2];
    const float* cont = (const float*)d_in[3];
    const int*   er   = (const int*)d_in[4];
    const int*   ec   = (const int*)d_in[5];
    const float* ev   = (const float*)d_in[6];
    const float* memb = (const float*)d_in[7];
    const float* wemb = (const float*)d_in[8];
    const float* temb = (const float*)d_in[9];
    const float* W1   = (const float*)d_in[10];
    const float* b1   = (const float*)d_in[11];
    const float* W2   = (const float*)d_in[12];
    const float* b2   = (const float*)d_in[13];
    const float* Wself  = (const float*)d_in[14];
    const float* bself  = (const float*)d_in[15];
    const float* Wneigh = (const float*)d_in[16];
    const float* bneigh = (const float*)d_in[17];

    int n = in_sizes[0];
    int e = in_sizes[4];

    float* out = (float*)d_out;
    float* h = out + 256;

    cudaFuncSetAttribute(k_mlp_tc, cudaFuncAttributeMaxDynamicSharedMemorySize, SMEM_MLP_TC);
    cudaFuncSetAttribute(k_layer_tc, cudaFuncAttributeMaxDynamicSharedMemorySize, SMEM_TC);

    int ntile = (n + 127) / 128;
    int nchunk = (n + 1023) / 1024;

    void* cnt_ptr = nullptr;
    cudaGetSymbolAddress(&cnt_ptr, g_cnt);
    __half* wlh_base = nullptr;
    cudaGetSymbolAddress((void**)&wlh_base, g_wlh);
    __half* hb0 = nullptr; __half* hb1 = nullptr;
    cudaGetSymbolAddress((void**)&hb0, g_hb);
    cudaGetSymbolAddress((void**)&hb1, g_hb2);

    // persistent side stream + events (created once; host-side only)
    static cudaStream_t s_side = nullptr;
    static cudaEvent_t ev_fork = nullptr, ev_join = nullptr;
    static cudaEvent_t ev_sA[2] = {nullptr, nullptr}, ev_sB[2] = {nullptr, nullptr},
                       ev_L[2] = {nullptr, nullptr};
    if (!s_side) {
        cudaStreamCreateWithFlags(&s_side, cudaStreamNonBlocking);
        cudaEventCreateWithFlags(&ev_fork, cudaEventDisableTiming);
        cudaEventCreateWithFlags(&ev_join, cudaEventDisableTiming);
        for (int l = 0; l < 2; l++) {
            cudaEventCreateWithFlags(&ev_sA[l], cudaEventDisableTiming);
            cudaEventCreateWithFlags(&ev_sB[l], cudaEventDisableTiming);
            cudaEventCreateWithFlags(&ev_L[l], cudaEventDisableTiming);
        }
    }

    // fork: CSR chain on side stream, MLP chain on main stream
    cudaEventRecord(ev_fork, 0);
    cudaStreamWaitEvent(s_side, ev_fork, 0);

    cudaMemsetAsync(cnt_ptr, 0, (size_t)n * sizeof(int), s_side);
    k_hist<<<(e / 4 + 255) / 256, 256, 0, s_side>>>(er, e);
    k_scanA<<<nchunk, 256, 0, s_side>>>(n);
    k_scanB<<<1, 256, 0, s_side>>>(nchunk, n);
    k_scanC<<<nchunk, 256, 0, s_side>>>(n);
    k_reorder<<<(e / 4 + 255) / 256, 256, 0, s_side>>>(er, ec, ev, e);
    cudaEventRecord(ev_join, s_side);

    k_prep<<<(64 * 128 + 128 * 128 + 2 * 256 * 128 + 255) / 256, 256>>>(W1, W2, Wself, Wneigh);
    k_mlp_tc<<<ntile, 256, SMEM_MLP_TC>>>(mi, wi, ti, cont, memb, wemb, temb, b1, b2, h, n);

    // join: spmm needs both CSR (side) and g_hb (main)
    cudaStreamWaitEvent(0, ev_join, 0);

    // half-chunk split (A = [0, nmid), B = [nmid, n)), nmid multiple of 128
    int tilesA = (ntile + 1) / 2;
    int nmid = tilesA * 128;
    if (nmid > n) nmid = n;
    int tilesB = ntile - tilesA;
    int rowsA = nmid, rowsB = n - nmid;
    int blkA = (rowsA * 16 + 255) / 256;
    int blkB = (rowsB * 16 + 255) / 256;

    const __half* hb_in[2]  = {hb0, hb1};
    __half*       hb_outp[2] = {hb1, nullptr};

    for (int l = 0; l < 2; l++) {
        // main: spmm chunk A, then chunk B
        k_spmm<<<blkA, 256>>>(hb_in[l], 0, nmid);
        cudaEventRecord(ev_sA[l], 0);
        if (blkB > 0) k_spmm<<<blkB, 256>>>(hb_in[l], nmid, n);
        cudaEventRecord(ev_sB[l], 0);

        // side: layer chunk A (overlaps spmm chunk B), then layer chunk B
        cudaStreamWaitEvent(s_side, ev_sA[l], 0);
        k_layer_tc<<<tilesA, 256, SMEM_TC, s_side>>>(
            wlh_base + (size_t)l * 256 * 128, bself + l * 128, bneigh + l * 128,
            h, hb_in[l], hb_outp[l], 0, n, l == 0 ? 1 : 0, l == 1 ? 1 : 0);
        cudaStreamWaitEvent(s_side, ev_sB[l], 0);
        if (tilesB > 0)
            k_layer_tc<<<tilesB, 256, SMEM_TC, s_side>>>(
                wlh_base + (size_t)l * 256 * 128, bself + l * 128, bneigh + l * 128,
                h, hb_in[l], hb_outp[l], nmid, n, l == 0 ? 1 : 0, l == 1 ? 1 : 0);
        cudaEventRecord(ev_L[l], s_side);

        // main must wait for full layer before next spmm generation
        cudaStreamWaitEvent(0, ev_L[l], 0);
    }

    k_final<<<1, 256>>>(out, n);
}

// round 13
// speedup vs baseline: 1.2709x; 1.2709x over previous
#include <cuda_runtime.h>
#include <cuda_fp16.h>

#define NMAX 200000
#define EMAX 6400000
#define HD 128

// ---------------- mma / ldmatrix helpers ------------------------------------
__device__ __forceinline__ unsigned smem_u32(const void* p) {
    return (unsigned)__cvta_generic_to_shared(p);
}
__device__ __forceinline__ void ldsm_x4(unsigned& r0, unsigned& r1, unsigned& r2, unsigned& r3,
                                        unsigned addr) {
    asm volatile("ldmatrix.sync.aligned.m8n8.x4.shared.b16 {%0,%1,%2,%3}, [%4];"
                 : "=r"(r0), "=r"(r1), "=r"(r2), "=r"(r3) : "r"(addr));
}
__device__ __forceinline__ void ldsm_x4_trans(unsigned& r0, unsigned& r1, unsigned& r2, unsigned& r3,
                                              unsigned addr) {
    asm volatile("ldmatrix.sync.aligned.m8n8.x4.trans.shared.b16 {%0,%1,%2,%3}, [%4];"
                 : "=r"(r0), "=r"(r1), "=r"(r2), "=r"(r3) : "r"(addr));
}
__device__ __forceinline__ void mma16816(float* d, unsigned a0, unsigned a1, unsigned a2, unsigned a3,
                                         unsigned b0, unsigned b1) {
    asm volatile("mma.sync.aligned.m16n8k16.row.col.f32.f16.f16.f32 "
                 "{%0,%1,%2,%3}, {%4,%5,%6,%7}, {%8,%9}, {%0,%1,%2,%3};"
                 : "+f"(d[0]), "+f"(d[1]), "+f"(d[2]), "+f"(d[3])
                 : "r"(a0), "r"(a1), "r"(a2), "r"(a3), "r"(b0), "r"(b1));
}

// ---------------- static device scratch (no allocations allowed) ------------
__device__ int g_cnt[NMAX];
__device__ int g_rowptr[NMAX + 1];
__device__ int g_cur[NMAX];
__device__ int g_part[256];
__device__ int g_partoff[256];
__device__ __align__(16) uint2 g_edges[EMAX];                 // (col, val-bits)
__device__ __align__(16) __half g_neighh[(size_t)NMAX * HD];  // fp16 neighbor agg
__device__ __align__(16) __half g_hb[(size_t)NMAX * HD];      // fp16 h gen-0 (MLP)
__device__ __align__(16) __half g_hb2[(size_t)NMAX * HD];     // fp16 h gen-1 (layer0)
__device__ __align__(16) __half g_w1h[64 * 128];              // padded W1 fp16
__device__ __align__(16) __half g_w2h[128 * 128];
__device__ __align__(16) __half g_wlh[2 * 256 * 128];         // [l][Ws;Wn][128]
__device__ float g_gsum[HD];
__device__ unsigned g_gmax[HD];

// ---------------- weight fp16 pre-conversion --------------------------------
__global__ void k_prep(const float* __restrict__ W1, const float* __restrict__ W2,
                       const float* __restrict__ Wself, const float* __restrict__ Wneigh) {
    int i = blockIdx.x * blockDim.x + threadIdx.x;
    if (i < 64 * 128) {
        int r = i >> 7, c = i & 127;
        g_w1h[i] = __float2half(r < 60 ? W1[r * 128 + c] : 0.f);
    } else if (i < 64 * 128 + 128 * 128) {
        int j = i - 64 * 128;
        g_w2h[j] = __float2half(W2[j]);
    } else if (i < 64 * 128 + 128 * 128 + 2 * 256 * 128) {
        int j = i - 64 * 128 - 128 * 128;
        int l = j >> 15;
        int r = (j & 32767) >> 7;
        int c = j & 127;
        float v = (r < 128) ? Wself[l * 16384 + r * 128 + c]
                            : Wneigh[l * 16384 + (r - 128) * 128 + c];
        g_wlh[j] = __float2half(v);
    }
}

// ---------------- CSR build: histogram -> parallel scan -> reorder ----------
__global__ void k_hist(const int* __restrict__ er, int e) {
    int i = blockIdx.x * blockDim.x + threadIdx.x;
    int i4 = i * 4;
    if (i4 + 3 < e) {
        int4 r = *(const int4*)&er[i4];
        atomicAdd(&g_cnt[r.x], 1);
        atomicAdd(&g_cnt[r.y], 1);
        atomicAdd(&g_cnt[r.z], 1);
        atomicAdd(&g_cnt[r.w], 1);
    } else {
        for (int j = i4; j < e; j++) atomicAdd(&g_cnt[er[j]], 1);
    }
}

__global__ void k_scanA(int n) {
    __shared__ int s[256];
    int b = blockIdx.x, t = threadIdx.x;
    int i0 = b * 1024 + t * 4;
    int sum = 0;
    #pragma unroll
    for (int j = 0; j < 4; j++) { int i = i0 + j; if (i < n) sum += g_cnt[i]; }
    s[t] = sum;
    __syncthreads();
    for (int off = 128; off > 0; off >>= 1) {
        if (t < off) s[t] += s[t + off];
        __syncthreads();
    }
    if (t == 0) g_part[b] = s[0];
}

__global__ void k_scanB(int nb, int n) {
    __shared__ int s[256];
    int t = threadIdx.x;
    if (t < HD) { g_gsum[t] = 0.f; g_gmax[t] = 0u; }
    int v = (t < nb) ? g_part[t] : 0;
    s[t] = v;
    __syncthreads();
    for (int off = 1; off < 256; off <<= 1) {
        int u = (t >= off) ? s[t - off] : 0;
        __syncthreads();
        s[t] += u;
        __syncthreads();
    }
    if (t < nb) g_partoff[t] = s[t] - v;
    if (t == 255) g_rowptr[n] = s[255];
}

__global__ void k_scanC(int n) {
    __shared__ int s[256];
    int b = blockIdx.x, t = threadIdx.x;
    int i0 = b * 1024 + t * 4;
    int c[4]; int sum = 0;
    #pragma unroll
    for (int j = 0; j < 4; j++) { int i = i0 + j; c[j] = (i < n) ? g_cnt[i] : 0; sum += c[j]; }
    s[t] = sum;
    __syncthreads();
    for (int off = 1; off < 256; off <<= 1) {
        int u = (t >= off) ? s[t - off] : 0;
        __syncthreads();
        s[t] += u;
        __syncthreads();
    }
    int pre = g_partoff[b] + s[t] - sum;
    #pragma unroll
    for (int j = 0; j < 4; j++) {
        int i = i0 + j;
        if (i < n) { g_rowptr[i] = pre; g_cur[i] = pre; pre += c[j]; }
    }
}

__global__ void k_reorder(const int* __restrict__ er, const int* __restrict__ ec,
                          const float* __restrict__ ev, int e) {
    int i = blockIdx.x * blockDim.x + threadIdx.x;
    int i4 = i * 4;
    if (i4 + 3 < e) {
        int4 r = *(const int4*)&er[i4];
        int4 c = *(const int4*)&ec[i4];
        float4 v = *(const float4*)&ev[i4];
        int p0 = atomicAdd(&g_cur[r.x], 1);
        int p1 = atomicAdd(&g_cur[r.y], 1);
        int p2 = atomicAdd(&g_cur[r.z], 1);
        int p3 = atomicAdd(&g_cur[r.w], 1);
        g_edges[p0] = make_uint2((unsigned)c.x, __float_as_uint(v.x));
        g_edges[p1] = make_uint2((unsigned)c.y, __float_as_uint(v.y));
        g_edges[p2] = make_uint2((unsigned)c.z, __float_as_uint(v.z));
        g_edges[p3] = make_uint2((unsigned)c.w, __float_as_uint(v.w));
    } else {
        for (int j = i4; j < e; j++) {
            int p = atomicAdd(&g_cur[er[j]], 1);
            g_edges[p] = make_uint2((unsigned)ec[j], __float_as_uint(ev[j]));
        }
    }
}

// ---------------- tensor-core input MLP (fp16-out only) ---------------------
#define XSTR 72
#define WSTR 136
#define SMEM_MLP_TC ((128 * XSTR + 64 * WSTR + 128 * WSTR + 128 * WSTR) * 2)

__global__ void __launch_bounds__(256, 1) k_mlp_tc(
    const int* __restrict__ mi, const int* __restrict__ wi, const int* __restrict__ ti,
    const float* __restrict__ cont,
    const float* __restrict__ memb, const float* __restrict__ wemb, const float* __restrict__ temb,
    const float* __restrict__ b1, const float* __restrict__ b2, int n)
{
    extern __shared__ __half smh[];
    __half* sX  = smh;
    __half* sW1 = sX + 128 * XSTR;
    __half* sW2 = sW1 + 64 * WSTR;
    __half* sH1 = sW2 + 128 * WSTR;

    int tid = threadIdx.x;
    int base = blockIdx.x * 128;

    for (int i = tid; i < 64 * 16; i += 256) {
        int r = i >> 4, q = i & 15;
        *(uint4*)&sW1[r * WSTR + q * 8] = *(const uint4*)&g_w1h[i * 8];
    }
    for (int i = tid; i < 128 * 16; i += 256) {
        int r = i >> 4, q = i & 15;
        *(uint4*)&sW2[r * WSTR + q * 8] = *(const uint4*)&g_w2h[i * 8];
    }
    for (int i = tid; i < 128 * 64; i += 256) {
        int nd = i >> 6, f = i & 63;
        int node = base + nd;
        float v = 0.f;
        if (node < n && f < 60) {
            if (f < 16)       v = memb[mi[node] * 16 + f];
            else if (f < 32)  v = wemb[wi[node] * 16 + (f - 16)];
            else if (f < 48)  v = temb[ti[node] * 16 + (f - 32)];
            else              v = cont[(size_t)node * 12 + (f - 48)];
        }
        sX[nd * XSTR + f] = __float2half(v);
    }
    __syncthreads();

    int wid = tid >> 5;
    int lane = tid & 31;
    int m0 = wid * 16;
    int lg = lane >> 3, lr = lane & 7;
    int a_row = m0 + lr + (lg & 1) * 8;
    int a_colb = (lg >> 1) * 8;
    int b_rowb = lr + (lg & 1) * 8;
    int b_colb = (lg >> 1) * 8;
    int row0 = m0 + (lane >> 2);
    int cbase = (lane & 3) * 2;

    unsigned sX_b = smem_u32(sX);
    unsigned sW1_b = smem_u32(sW1);
    unsigned sW2_b = smem_u32(sW2);
    unsigned sH1_b = smem_u32(sH1);

    float acc[16][4];
    #pragma unroll
    for (int t = 0; t < 16; t++)
        #pragma unroll
        for (int c = 0; c < 4; c++) acc[t][c] = 0.f;

    #pragma unroll
    for (int ks = 0; ks < 4; ks++) {
        int k0 = ks * 16;
        unsigned a0, a1, a2, a3;
        ldsm_x4(a0, a1, a2, a3, sX_b + (unsigned)(a_row * XSTR + k0 + a_colb) * 2u);
        #pragma unroll
        for (int j = 0; j < 8; j++) {
            unsigned b0, b1r, b2r, b3;
            ldsm_x4_trans(b0, b1r, b2r, b3,
                          sW1_b + (unsigned)((k0 + b_rowb) * WSTR + j * 16 + b_colb) * 2u);
            mma16816(acc[2 * j], a0, a1, a2, a3, b0, b1r);
            mma16816(acc[2 * j + 1], a0, a1, a2, a3, b2r, b3);
        }
    }
    #pragma unroll
    for (int t = 0; t < 16; t++) {
        int col = t * 8 + cbase;
        float bb0 = b1[col], bb1 = b1[col + 1];
        __half2 h0 = __floats2half2_rn(fmaxf(acc[t][0] + bb0, 0.f), fmaxf(acc[t][1] + bb1, 0.f));
        __half2 h1v = __floats2half2_rn(fmaxf(acc[t][2] + bb0, 0.f), fmaxf(acc[t][3] + bb1, 0.f));
        *(__half2*)&sH1[row0 * WSTR + col] = h0;
        *(__half2*)&sH1[(row0 + 8) * WSTR + col] = h1v;
    }
    __syncthreads();

    #pragma unroll
    for (int t = 0; t < 16; t++)
        #pragma unroll
        for (int c = 0; c < 4; c++) acc[t][c] = 0.f;

    #pragma unroll 1
    for (int ks = 0; ks < 8; ks++) {
        int k0 = ks * 16;
        unsigned a0, a1, a2, a3;
        ldsm_x4(a0, a1, a2, a3, sH1_b + (unsigned)(a_row * WSTR + k0 + a_colb) * 2u);
        #pragma unroll
        for (int j = 0; j < 8; j++) {
            unsigned b0, b1r, b2r, b3;
            ldsm_x4_trans(b0, b1r, b2r, b3,
                          sW2_b + (unsigned)((k0 + b_rowb) * WSTR + j * 16 + b_colb) * 2u);
            mma16816(acc[2 * j], a0, a1, a2, a3, b0, b1r);
            mma16816(acc[2 * j + 1], a0, a1, a2, a3, b2r, b3);
        }
    }
    int node0 = base + row0;
    int node1 = node0 + 8;
    #pragma unroll
    for (int t = 0; t < 16; t++) {
        int col = t * 8 + cbase;
        float bb0 = b2[col], bb1 = b2[col + 1];
        if (node0 < n) {
            float x = fmaxf(acc[t][0] + bb0, 0.f);
            float y = fmaxf(acc[t][1] + bb1, 0.f);
            *(__half2*)&g_hb[(size_t)node0 * 128 + col] = __floats2half2_rn(x, y);
        }
        if (node1 < n) {
            float x = fmaxf(acc[t][2] + bb0, 0.f);
            float y = fmaxf(acc[t][3] + bb1, 0.f);
            *(__half2*)&g_hb[(size_t)node1 * 128 + col] = __floats2half2_rn(x, y);
        }
    }
}

// ---------------- SpMM: half-warp per row, fp16 in, fp16 out (R6 proven) ----
__global__ void k_spmm(const __half* __restrict__ hb, int n) {
    int row = (blockIdx.x * blockDim.x + threadIdx.x) >> 4;
    if (row >= n) return;
    int s = threadIdx.x & 15;
    int beg = g_rowptr[row], end = g_rowptr[row + 1];
    float acc0 = 0.f, acc1 = 0.f, acc2 = 0.f, acc3 = 0.f;
    float acc4 = 0.f, acc5 = 0.f, acc6 = 0.f, acc7 = 0.f;
    int e = beg;
    for (; e + 1 < end; e += 2) {
        uint2 e0 = __ldcs(&g_edges[e]);
        uint2 e1 = __ldcs(&g_edges[e + 1]);
        float v0 = __uint_as_float(e0.y);
        float v1 = __uint_as_float(e1.y);
        uint4 x0 = *(const uint4*)&hb[(size_t)e0.x * 128 + s * 8];
        uint4 x1 = *(const uint4*)&hb[(size_t)e1.x * 128 + s * 8];
        float2 p;
        p = __half22float2(*(__half2*)&x0.x); acc0 += v0 * p.x; acc1 += v0 * p.y;
        p = __half22float2(*(__half2*)&x0.y); acc2 += v0 * p.x; acc3 += v0 * p.y;
        p = __half22float2(*(__half2*)&x0.z); acc4 += v0 * p.x; acc5 += v0 * p.y;
        p = __half22float2(*(__half2*)&x0.w); acc6 += v0 * p.x; acc7 += v0 * p.y;
        p = __half22float2(*(__half2*)&x1.x); acc0 += v1 * p.x; acc1 += v1 * p.y;
        p = __half22float2(*(__half2*)&x1.y); acc2 += v1 * p.x; acc3 += v1 * p.y;
        p = __half22float2(*(__half2*)&x1.z); acc4 += v1 * p.x; acc5 += v1 * p.y;
        p = __half22float2(*(__half2*)&x1.w); acc6 += v1 * p.x; acc7 += v1 * p.y;
    }
    if (e < end) {
        uint2 e0 = __ldcs(&g_edges[e]);
        float v0 = __uint_as_float(e0.y);
        uint4 x0 = *(const uint4*)&hb[(size_t)e0.x * 128 + s * 8];
        float2 p;
        p = __half22float2(*(__half2*)&x0.x); acc0 += v0 * p.x; acc1 += v0 * p.y;
        p = __half22float2(*(__half2*)&x0.y); acc2 += v0 * p.x; acc3 += v0 * p.y;
        p = __half22float2(*(__half2*)&x0.z); acc4 += v0 * p.x; acc5 += v0 * p.y;
        p = __half22float2(*(__half2*)&x0.w); acc6 += v0 * p.x; acc7 += v0 * p.y;
    }
    uint4 o;
    __half2 h0 = __floats2half2_rn(acc0, acc1);
    __half2 h1 = __floats2half2_rn(acc2, acc3);
    __half2 h2 = __floats2half2_rn(acc4, acc5);
    __half2 h3 = __floats2half2_rn(acc6, acc7);
    o.x = *(unsigned*)&h0; o.y = *(unsigned*)&h1;
    o.z = *(unsigned*)&h2; o.w = *(unsigned*)&h3;
    __stcs((uint4*)&g_neighh[(size_t)row * 128 + s * 8], o);
}

// ---------------- tensor-core layer: residual from smem, fp16 carry ---------
#define ASTR 264
#define SMEM_TC ((256 * WSTR + 128 * ASTR) * 2)

__global__ void __launch_bounds__(256, 1) k_layer_tc(
    const __half* __restrict__ wl, const float* __restrict__ bs, const float* __restrict__ bn,
    const __half* __restrict__ hb_in, __half* __restrict__ hb_out,
    float* __restrict__ hout, int n, int last)
{
    extern __shared__ __half smh[];
    __half* sW = smh;
    __half* sA = smh + 256 * WSTR;
    __shared__ float psum[8][HD];
    __shared__ unsigned pmax[8][HD];

    int tid = threadIdx.x;
    int base = blockIdx.x * 128;

    for (int i = tid; i < 256 * 16; i += 256) {
        int r = i >> 4, q = i & 15;
        *(uint4*)&sW[r * WSTR + q * 8] = *(const uint4*)&wl[i * 8];
    }
    for (int i = tid; i < 128 * 32; i += 256) {
        int nd = i >> 5, q = i & 31;
        int node = base + nd;
        uint4 v = {0u, 0u, 0u, 0u};
        if (node < n) {
            if (q < 16) v = *(const uint4*)&hb_in[(size_t)node * 128 + q * 8];
            else        v = *(const uint4*)&g_neighh[(size_t)node * 128 + (q - 16) * 8];
        }
        *(uint4*)&sA[nd * ASTR + q * 8] = v;
    }
    __syncthreads();

    int wid = tid >> 5;
    int lane = tid & 31;
    int m0 = wid * 16;
    int lg = lane >> 3, lr = lane & 7;
    int a_row = m0 + lr + (lg & 1) * 8;
    int a_colb = (lg >> 1) * 8;
    int b_rowb = lr + (lg & 1) * 8;
    int b_colb = (lg >> 1) * 8;

    unsigned sA_b = smem_u32(sA);
    unsigned sW_b = smem_u32(sW);

    float acc[16][4];
    #pragma unroll
    for (int t = 0; t < 16; t++)
        #pragma unroll
        for (int c = 0; c < 4; c++) acc[t][c] = 0.f;

    #pragma unroll 1
    for (int ks = 0; ks < 16; ks++) {
        int k0 = ks * 16;
        unsigned a0, a1, a2, a3;
        ldsm_x4(a0, a1, a2, a3, sA_b + (unsigned)(a_row * ASTR + k0 + a_colb) * 2u);
        #pragma unroll
        for (int j = 0; j < 8; j++) {
            unsigned b0, b1, b2, b3;
            ldsm_x4_trans(b0, b1, b2, b3,
                          sW_b + (unsigned)((k0 + b_rowb) * WSTR + j * 16 + b_colb) * 2u);
            mma16816(acc[2 * j], a0, a1, a2, a3, b0, b1);
            mma16816(acc[2 * j + 1], a0, a1, a2, a3, b2, b3);
        }
    }

    int row0 = m0 + (lane >> 2);
    int cbase = (lane & 3) * 2;
    int node0 = base + row0;
    int node1 = node0 + 8;
    #pragma unroll
    for (int t = 0; t < 16; t++) {
        int col = t * 8 + cbase;
        float bsum0 = bs[col] + bn[col];
        float bsum1 = bs[col + 1] + bn[col + 1];
        float s0 = 0.f, s1 = 0.f, m0v = 0.f, m1v = 0.f;
        // residual base from the staged fp16 A-tile (no global read)
        float2 p0 = __half22float2(*(__half2*)&sA[row0 * ASTR + col]);
        float2 p1 = __half22float2(*(__half2*)&sA[(row0 + 8) * ASTR + col]);
        if (node0 < n) {
            float hx = p0.x + fmaxf(acc[t][0] + bsum0, 0.f);
            float hy = p0.y + fmaxf(acc[t][1] + bsum1, 0.f);
            size_t off = (size_t)node0 * 128 + col;
            if (last) *(float2*)&hout[off] = make_float2(hx, hy);
            else      *(__half2*)&hb_out[off] = __floats2half2_rn(hx, hy);
            s0 += hx; s1 += hy;
            m0v = fmaxf(m0v, hx); m1v = fmaxf(m1v, hy);
        }
        if (node1 < n) {
            float hx = p1.x + fmaxf(acc[t][2] + bsum0, 0.f);
            float hy = p1.y + fmaxf(acc[t][3] + bsum1, 0.f);
            size_t off = (size_t)node1 * 128 + col;
            if (last) *(float2*)&hout[off] = make_float2(hx, hy);
            else      *(__half2*)&hb_out[off] = __floats2half2_rn(hx, hy);
            s0 += hx; s1 += hy;
            m0v = fmaxf(m0v, hx); m1v = fmaxf(m1v, hy);
        }
        if (last) {
            #pragma unroll
            for (int o = 16; o >= 4; o >>= 1) {
                s0 += __shfl_down_sync(0xffffffffu, s0, o);
                s1 += __shfl_down_sync(0xffffffffu, s1, o);
                m0v = fmaxf(m0v, __shfl_down_sync(0xffffffffu, m0v, o));
                m1v = fmaxf(m1v, __shfl_down_sync(0xffffffffu, m1v, o));
            }
            if (lane < 4) {
                psum[wid][col] = s0;
                psum[wid][col + 1] = s1;
                pmax[wid][col] = __float_as_uint(m0v);
                pmax[wid][col + 1] = __float_as_uint(m1v);
            }
        }
    }
    if (last) {
        __syncthreads();
        if (tid < HD) {
            float s = 0.f;
            unsigned m = 0u;
            #pragma unroll
            for (int w = 0; w < 8; w++) {
                s += psum[w][tid];
                m = max(m, pmax[w][tid]);
            }
            atomicAdd(&g_gsum[tid], s);
            atomicMax(&g_gmax[tid], m);
        }
    }
}

// ---------------- final: write pooled output --------------------------------
__global__ void k_final(float* __restrict__ out, int n) {
    int t = threadIdx.x;  // 256
    if (t < 128) out[t] = g_gsum[t] / (float)n;
    else out[t] = __uint_as_float(g_gmax[t - 128]);
}

// ---------------- launch -----------------------------------------------------
extern "C" void kernel_launch(void* const* d_in, const int* in_sizes, int n_in,
                              void* d_out, int out_size) {
    const int*   mi   = (const int*)d_in[0];
    const int*   wi   = (const int*)d_in[1];
    const int*   ti   = (const int*)d_in[2];
    const float* cont = (const float*)d_in[3];
    const int*   er   = (const int*)d_in[4];
    const int*   ec   = (const int*)d_in[5];
    const float* ev   = (const float*)d_in[6];
    const float* memb = (const float*)d_in[7];
    const float* wemb = (const float*)d_in[8];
    const float* temb = (const float*)d_in[9];
    const float* W1   = (const float*)d_in[10];
    const float* b1   = (const float*)d_in[11];
    const float* W2   = (const float*)d_in[12];
    const float* b2   = (const float*)d_in[13];
    const float* Wself  = (const float*)d_in[14];
    const float* bself  = (const float*)d_in[15];
    const float* Wneigh = (const float*)d_in[16];
    const float* bneigh = (const float*)d_in[17];

    int n = in_sizes[0];
    int e = in_sizes[4];

    float* out = (float*)d_out;
    float* h = out + 256;

    cudaFuncSetAttribute(k_mlp_tc, cudaFuncAttributeMaxDynamicSharedMemorySize, SMEM_MLP_TC);
    cudaFuncSetAttribute(k_layer_tc, cudaFuncAttributeMaxDynamicSharedMemorySize, SMEM_TC);

    int ntile = (n + 127) / 128;
    int nchunk = (n + 1023) / 1024;

    void* cnt_ptr = nullptr;
    cudaGetSymbolAddress(&cnt_ptr, g_cnt);
    __half* wlh_base = nullptr;
    cudaGetSymbolAddress((void**)&wlh_base, g_wlh);
    __half* hb0 = nullptr; __half* hb1 = nullptr;
    cudaGetSymbolAddress((void**)&hb0, g_hb);
    cudaGetSymbolAddress((void**)&hb1, g_hb2);

    // persistent side stream + events for fork-join (created once; host-side only)
    static cudaStream_t s_csr = nullptr;
    static cudaEvent_t ev_fork = nullptr, ev_join = nullptr;
    if (!s_csr) {
        cudaStreamCreateWithFlags(&s_csr, cudaStreamNonBlocking);
        cudaEventCreateWithFlags(&ev_fork, cudaEventDisableTiming);
        cudaEventCreateWithFlags(&ev_join, cudaEventDisableTiming);
    }

    // fork: CSR chain on side stream, MLP chain on main stream
    cudaEventRecord(ev_fork, 0);
    cudaStreamWaitEvent(s_csr, ev_fork, 0);

    cudaMemsetAsync(cnt_ptr, 0, (size_t)n * sizeof(int), s_csr);
    k_hist<<<(e / 4 + 255) / 256, 256, 0, s_csr>>>(er, e);
    k_scanA<<<nchunk, 256, 0, s_csr>>>(n);
    k_scanB<<<1, 256, 0, s_csr>>>(nchunk, n);
    k_scanC<<<nchunk, 256, 0, s_csr>>>(n);
    k_reorder<<<(e / 4 + 255) / 256, 256, 0, s_csr>>>(er, ec, ev, e);
    cudaEventRecord(ev_join, s_csr);

    k_prep<<<(64 * 128 + 128 * 128 + 2 * 256 * 128 + 255) / 256, 256>>>(W1, W2, Wself, Wneigh);
    k_mlp_tc<<<ntile, 256, SMEM_MLP_TC>>>(mi, wi, ti, cont, memb, wemb, temb, b1, b2, n);

    // join: spmm needs both CSR (side) and g_hb (main)
    cudaStreamWaitEvent(0, ev_join, 0);

    int hw_blocks = (int)(((long long)n * 16 + 255) / 256);

    // layer 0: hb0 -> hb1 (fp16 carry)
    k_spmm<<<hw_blocks, 256>>>(hb0, n);
    k_layer_tc<<<ntile, 256, SMEM_TC>>>(wlh_base, bself, bneigh, hb0, hb1, nullptr, n, 0);

    // layer 1: hb1 -> h (fp32 final) + fused pool
    k_spmm<<<hw_blocks, 256>>>(hb1, n);
    k_layer_tc<<<ntile, 256, SMEM_TC>>>(wlh_base + (size_t)256 * 128, bself + 128, bneigh + 128,
                                        hb1, nullptr, h, n, 1);

    k_final<<<1, 256>>>(out, n);
}

// round 14
// speedup vs baseline: 1.2986x; 1.0218x over previous
#include <cuda_runtime.h>
#include <cuda_fp16.h>

#define NMAX 200000
#define EMAX 6400000
#define HD 128

// ---------------- mma / ldmatrix helpers ------------------------------------
__device__ __forceinline__ unsigned smem_u32(const void* p) {
    return (unsigned)__cvta_generic_to_shared(p);
}
__device__ __forceinline__ void ldsm_x4(unsigned& r0, unsigned& r1, unsigned& r2, unsigned& r3,
                                        unsigned addr) {
    asm volatile("ldmatrix.sync.aligned.m8n8.x4.shared.b16 {%0,%1,%2,%3}, [%4];"
                 : "=r"(r0), "=r"(r1), "=r"(r2), "=r"(r3) : "r"(addr));
}
__device__ __forceinline__ void ldsm_x4_trans(unsigned& r0, unsigned& r1, unsigned& r2, unsigned& r3,
                                              unsigned addr) {
    asm volatile("ldmatrix.sync.aligned.m8n8.x4.trans.shared.b16 {%0,%1,%2,%3}, [%4];"
                 : "=r"(r0), "=r"(r1), "=r"(r2), "=r"(r3) : "r"(addr));
}
__device__ __forceinline__ void mma16816(float* d, unsigned a0, unsigned a1, unsigned a2, unsigned a3,
                                         unsigned b0, unsigned b1) {
    asm volatile("mma.sync.aligned.m16n8k16.row.col.f32.f16.f16.f32 "
                 "{%0,%1,%2,%3}, {%4,%5,%6,%7}, {%8,%9}, {%0,%1,%2,%3};"
                 : "+f"(d[0]), "+f"(d[1]), "+f"(d[2]), "+f"(d[3])
                 : "r"(a0), "r"(a1), "r"(a2), "r"(a3), "r"(b0), "r"(b1));
}

// ---------------- static device scratch (no allocations allowed) ------------
__device__ int g_cnt[NMAX];
__device__ int g_rowptr[NMAX + 1];
__device__ int g_cur[NMAX];
__device__ int g_part[256];
__device__ int g_partoff[256];
__device__ __align__(16) uint2 g_edges[EMAX];                 // (col, val-bits)
__device__ __align__(16) __half g_neighh[(size_t)NMAX * HD];  // fp16 neighbor agg
__device__ __align__(16) __half g_hb[(size_t)NMAX * HD];      // fp16 h gen-0 (MLP)
__device__ __align__(16) __half g_hb2[(size_t)NMAX * HD];     // fp16 h gen-1 (layer0)
__device__ __align__(16) __half g_w1h[64 * 128];              // padded W1 fp16
__device__ __align__(16) __half g_w2h[128 * 128];
__device__ __align__(16) __half g_wlh[2 * 256 * 128];         // [l][Ws;Wn][128]
__device__ float g_gsum[HD];
__device__ unsigned g_gmax[HD];

// ---------------- weight fp16 pre-conversion --------------------------------
__global__ void k_prep(const float* __restrict__ W1, const float* __restrict__ W2,
                       const float* __restrict__ Wself, const float* __restrict__ Wneigh) {
    int i = blockIdx.x * blockDim.x + threadIdx.x;
    if (i < 64 * 128) {
        int r = i >> 7, c = i & 127;
        g_w1h[i] = __float2half(r < 60 ? W1[r * 128 + c] : 0.f);
    } else if (i < 64 * 128 + 128 * 128) {
        int j = i - 64 * 128;
        g_w2h[j] = __float2half(W2[j]);
    } else if (i < 64 * 128 + 128 * 128 + 2 * 256 * 128) {
        int j = i - 64 * 128 - 128 * 128;
        int l = j >> 15;
        int r = (j & 32767) >> 7;
        int c = j & 127;
        float v = (r < 128) ? Wself[l * 16384 + r * 128 + c]
                            : Wneigh[l * 16384 + (r - 128) * 128 + c];
        g_wlh[j] = __float2half(v);
    }
}

// ---------------- CSR build: histogram -> parallel scan -> reorder ----------
__global__ void k_hist(const int* __restrict__ er, int e) {
    int i = blockIdx.x * blockDim.x + threadIdx.x;
    int i4 = i * 4;
    if (i4 + 3 < e) {
        int4 r = *(const int4*)&er[i4];
        atomicAdd(&g_cnt[r.x], 1);
        atomicAdd(&g_cnt[r.y], 1);
        atomicAdd(&g_cnt[r.z], 1);
        atomicAdd(&g_cnt[r.w], 1);
    } else {
        for (int j = i4; j < e; j++) atomicAdd(&g_cnt[er[j]], 1);
    }
}

__global__ void k_scanA(int n) {
    __shared__ int s[256];
    int b = blockIdx.x, t = threadIdx.x;
    int i0 = b * 1024 + t * 4;
    int sum = 0;
    #pragma unroll
    for (int j = 0; j < 4; j++) { int i = i0 + j; if (i < n) sum += g_cnt[i]; }
    s[t] = sum;
    __syncthreads();
    for (int off = 128; off > 0; off >>= 1) {
        if (t < off) s[t] += s[t + off];
        __syncthreads();
    }
    if (t == 0) g_part[b] = s[0];
}

__global__ void k_scanB(int nb, int n) {
    __shared__ int s[256];
    int t = threadIdx.x;
    if (t < HD) { g_gsum[t] = 0.f; g_gmax[t] = 0u; }
    int v = (t < nb) ? g_part[t] : 0;
    s[t] = v;
    __syncthreads();
    for (int off = 1; off < 256; off <<= 1) {
        int u = (t >= off) ? s[t - off] : 0;
        __syncthreads();
        s[t] += u;
        __syncthreads();
    }
    if (t < nb) g_partoff[t] = s[t] - v;
    if (t == 255) g_rowptr[n] = s[255];
}

__global__ void k_scanC(int n) {
    __shared__ int s[256];
    int b = blockIdx.x, t = threadIdx.x;
    int i0 = b * 1024 + t * 4;
    int c[4]; int sum = 0;
    #pragma unroll
    for (int j = 0; j < 4; j++) { int i = i0 + j; c[j] = (i < n) ? g_cnt[i] : 0; sum += c[j]; }
    s[t] = sum;
    __syncthreads();
    for (int off = 1; off < 256; off <<= 1) {
        int u = (t >= off) ? s[t - off] : 0;
        __syncthreads();
        s[t] += u;
        __syncthreads();
    }
    int pre = g_partoff[b] + s[t] - sum;
    #pragma unroll
    for (int j = 0; j < 4; j++) {
        int i = i0 + j;
        if (i < n) { g_rowptr[i] = pre; g_cur[i] = pre; pre += c[j]; }
    }
}

__global__ void k_reorder(const int* __restrict__ er, const int* __restrict__ ec,
                          const float* __restrict__ ev, int e) {
    int i = blockIdx.x * blockDim.x + threadIdx.x;
    int i4 = i * 4;
    if (i4 + 3 < e) {
        int4 r = *(const int4*)&er[i4];
        int4 c = *(const int4*)&ec[i4];
        float4 v = *(const float4*)&ev[i4];
        int p0 = atomicAdd(&g_cur[r.x], 1);
        int p1 = atomicAdd(&g_cur[r.y], 1);
        int p2 = atomicAdd(&g_cur[r.z], 1);
        int p3 = atomicAdd(&g_cur[r.w], 1);
        __stcs(&g_edges[p0], make_uint2((unsigned)c.x, __float_as_uint(v.x)));
        __stcs(&g_edges[p1], make_uint2((unsigned)c.y, __float_as_uint(v.y)));
        __stcs(&g_edges[p2], make_uint2((unsigned)c.z, __float_as_uint(v.z)));
        __stcs(&g_edges[p3], make_uint2((unsigned)c.w, __float_as_uint(v.w)));
    } else {
        for (int j = i4; j < e; j++) {
            int p = atomicAdd(&g_cur[er[j]], 1);
            __stcs(&g_edges[p], make_uint2((unsigned)ec[j], __float_as_uint(ev[j])));
        }
    }
}

// ---------------- tensor-core input MLP (fp16-out only) ---------------------
#define XSTR 72
#define WSTR 136
#define SMEM_MLP_TC ((128 * XSTR + 64 * WSTR + 128 * WSTR + 128 * WSTR) * 2)

__global__ void __launch_bounds__(256, 1) k_mlp_tc(
    const int* __restrict__ mi, const int* __restrict__ wi, const int* __restrict__ ti,
    const float* __restrict__ cont,
    const float* __restrict__ memb, const float* __restrict__ wemb, const float* __restrict__ temb,
    const float* __restrict__ b1, const float* __restrict__ b2, int n)
{
    extern __shared__ __half smh[];
    __half* sX  = smh;
    __half* sW1 = sX + 128 * XSTR;
    __half* sW2 = sW1 + 64 * WSTR;
    __half* sH1 = sW2 + 128 * WSTR;

    int tid = threadIdx.x;
    int base = blockIdx.x * 128;

    for (int i = tid; i < 64 * 16; i += 256) {
        int r = i >> 4, q = i & 15;
        *(uint4*)&sW1[r * WSTR + q * 8] = *(const uint4*)&g_w1h[i * 8];
    }
    for (int i = tid; i < 128 * 16; i += 256) {
        int r = i >> 4, q = i & 15;
        *(uint4*)&sW2[r * WSTR + q * 8] = *(const uint4*)&g_w2h[i * 8];
    }
    for (int i = tid; i < 128 * 64; i += 256) {
        int nd = i >> 6, f = i & 63;
        int node = base + nd;
        float v = 0.f;
        if (node < n && f < 60) {
            if (f < 16)       v = memb[mi[node] * 16 + f];
            else if (f < 32)  v = wemb[wi[node] * 16 + (f - 16)];
            else if (f < 48)  v = temb[ti[node] * 16 + (f - 32)];
            else              v = cont[(size_t)node * 12 + (f - 48)];
        }
        sX[nd * XSTR + f] = __float2half(v);
    }
    __syncthreads();

    int wid = tid >> 5;
    int lane = tid & 31;
    int m0 = wid * 16;
    int lg = lane >> 3, lr = lane & 7;
    int a_row = m0 + lr + (lg & 1) * 8;
    int a_colb = (lg >> 1) * 8;
    int b_rowb = lr + (lg & 1) * 8;
    int b_colb = (lg >> 1) * 8;
    int row0 = m0 + (lane >> 2);
    int cbase = (lane & 3) * 2;

    unsigned sX_b = smem_u32(sX);
    unsigned sW1_b = smem_u32(sW1);
    unsigned sW2_b = smem_u32(sW2);
    unsigned sH1_b = smem_u32(sH1);

    float acc[16][4];
    #pragma unroll
    for (int t = 0; t < 16; t++)
        #pragma unroll
        for (int c = 0; c < 4; c++) acc[t][c] = 0.f;

    #pragma unroll
    for (int ks = 0; ks < 4; ks++) {
        int k0 = ks * 16;
        unsigned a0, a1, a2, a3;
        ldsm_x4(a0, a1, a2, a3, sX_b + (unsigned)(a_row * XSTR + k0 + a_colb) * 2u);
        #pragma unroll
        for (int j = 0; j < 8; j++) {
            unsigned b0, b1r, b2r, b3;
            ldsm_x4_trans(b0, b1r, b2r, b3,
                          sW1_b + (unsigned)((k0 + b_rowb) * WSTR + j * 16 + b_colb) * 2u);
            mma16816(acc[2 * j], a0, a1, a2, a3, b0, b1r);
            mma16816(acc[2 * j + 1], a0, a1, a2, a3, b2r, b3);
        }
    }
    #pragma unroll
    for (int t = 0; t < 16; t++) {
        int col = t * 8 + cbase;
        float bb0 = b1[col], bb1 = b1[col + 1];
        __half2 h0 = __floats2half2_rn(fmaxf(acc[t][0] + bb0, 0.f), fmaxf(acc[t][1] + bb1, 0.f));
        __half2 h1v = __floats2half2_rn(fmaxf(acc[t][2] + bb0, 0.f), fmaxf(acc[t][3] + bb1, 0.f));
        *(__half2*)&sH1[row0 * WSTR + col] = h0;
        *(__half2*)&sH1[(row0 + 8) * WSTR + col] = h1v;
    }
    __syncthreads();

    #pragma unroll
    for (int t = 0; t < 16; t++)
        #pragma unroll
        for (int c = 0; c < 4; c++) acc[t][c] = 0.f;

    #pragma unroll 1
    for (int ks = 0; ks < 8; ks++) {
        int k0 = ks * 16;
        unsigned a0, a1, a2, a3;
        ldsm_x4(a0, a1, a2, a3, sH1_b + (unsigned)(a_row * WSTR + k0 + a_colb) * 2u);
        #pragma unroll
        for (int j = 0; j < 8; j++) {
            unsigned b0, b1r, b2r, b3;
            ldsm_x4_trans(b0, b1r, b2r, b3,
                          sW2_b + (unsigned)((k0 + b_rowb) * WSTR + j * 16 + b_colb) * 2u);
            mma16816(acc[2 * j], a0, a1, a2, a3, b0, b1r);
            mma16816(acc[2 * j + 1], a0, a1, a2, a3, b2r, b3);
        }
    }
    int node0 = base + row0;
    int node1 = node0 + 8;
    #pragma unroll
    for (int t = 0; t < 16; t++) {
        int col = t * 8 + cbase;
        float bb0 = b2[col], bb1 = b2[col + 1];
        if (node0 < n) {
            float x = fmaxf(acc[t][0] + bb0, 0.f);
            float y = fmaxf(acc[t][1] + bb1, 0.f);
            *(__half2*)&g_hb[(size_t)node0 * 128 + col] = __floats2half2_rn(x, y);
        }
        if (node1 < n) {
            float x = fmaxf(acc[t][2] + bb0, 0.f);
            float y = fmaxf(acc[t][3] + bb1, 0.f);
            *(__half2*)&g_hb[(size_t)node1 * 128 + col] = __floats2half2_rn(x, y);
        }
    }
}

// ---------------- SpMM: half-warp per row, fp16 in, fp16 out ----------------
__global__ void __launch_bounds__(512) k_spmm(const __half* __restrict__ hb, int n) {
    int row = (blockIdx.x * blockDim.x + threadIdx.x) >> 4;
    if (row >= n) return;
    int s = threadIdx.x & 15;
    int beg = g_rowptr[row], end = g_rowptr[row + 1];
    float acc0 = 0.f, acc1 = 0.f, acc2 = 0.f, acc3 = 0.f;
    float acc4 = 0.f, acc5 = 0.f, acc6 = 0.f, acc7 = 0.f;
    int e = beg;
    for (; e + 1 < end; e += 2) {
        uint2 e0 = __ldcs(&g_edges[e]);
        uint2 e1 = __ldcs(&g_edges[e + 1]);
        float v0 = __uint_as_float(e0.y);
        float v1 = __uint_as_float(e1.y);
        uint4 x0 = *(const uint4*)&hb[(size_t)e0.x * 128 + s * 8];
        uint4 x1 = *(const uint4*)&hb[(size_t)e1.x * 128 + s * 8];
        float2 p;
        p = __half22float2(*(__half2*)&x0.x); acc0 += v0 * p.x; acc1 += v0 * p.y;
        p = __half22float2(*(__half2*)&x0.y); acc2 += v0 * p.x; acc3 += v0 * p.y;
        p = __half22float2(*(__half2*)&x0.z); acc4 += v0 * p.x; acc5 += v0 * p.y;
        p = __half22float2(*(__half2*)&x0.w); acc6 += v0 * p.x; acc7 += v0 * p.y;
        p = __half22float2(*(__half2*)&x1.x); acc0 += v1 * p.x; acc1 += v1 * p.y;
        p = __half22float2(*(__half2*)&x1.y); acc2 += v1 * p.x; acc3 += v1 * p.y;
        p = __half22float2(*(__half2*)&x1.z); acc4 += v1 * p.x; acc5 += v1 * p.y;
        p = __half22float2(*(__half2*)&x1.w); acc6 += v1 * p.x; acc7 += v1 * p.y;
    }
    if (e < end) {
        uint2 e0 = __ldcs(&g_edges[e]);
        float v0 = __uint_as_float(e0.y);
        uint4 x0 = *(const uint4*)&hb[(size_t)e0.x * 128 + s * 8];
        float2 p;
        p = __half22float2(*(__half2*)&x0.x); acc0 += v0 * p.x; acc1 += v0 * p.y;
        p = __half22float2(*(__half2*)&x0.y); acc2 += v0 * p.x; acc3 += v0 * p.y;
        p = __half22float2(*(__half2*)&x0.z); acc4 += v0 * p.x; acc5 += v0 * p.y;
        p = __half22float2(*(__half2*)&x0.w); acc6 += v0 * p.x; acc7 += v0 * p.y;
    }
    uint4 o;
    __half2 h0 = __floats2half2_rn(acc0, acc1);
    __half2 h1 = __floats2half2_rn(acc2, acc3);
    __half2 h2 = __floats2half2_rn(acc4, acc5);
    __half2 h3 = __floats2half2_rn(acc6, acc7);
    o.x = *(unsigned*)&h0; o.y = *(unsigned*)&h1;
    o.z = *(unsigned*)&h2; o.w = *(unsigned*)&h3;
    __stcs((uint4*)&g_neighh[(size_t)row * 128 + s * 8], o);
}

// ---------------- tensor-core layer: residual from smem, fp16 carry ---------
#define ASTR 264
#define SMEM_TC ((256 * WSTR + 128 * ASTR) * 2)

__global__ void __launch_bounds__(256, 1) k_layer_tc(
    const __half* __restrict__ wl, const float* __restrict__ bs, const float* __restrict__ bn,
    const __half* __restrict__ hb_in, __half* __restrict__ hb_out,
    float* __restrict__ hout, int n, int last)
{
    extern __shared__ __half smh[];
    __half* sW = smh;
    __half* sA = smh + 256 * WSTR;
    __shared__ float psum[8][HD];
    __shared__ unsigned pmax[8][HD];

    int tid = threadIdx.x;
    int base = blockIdx.x * 128;

    for (int i = tid; i < 256 * 16; i += 256) {
        int r = i >> 4, q = i & 15;
        *(uint4*)&sW[r * WSTR + q * 8] = *(const uint4*)&wl[i * 8];
    }
    for (int i = tid; i < 128 * 32; i += 256) {
        int nd = i >> 5, q = i & 31;
        int node = base + nd;
        uint4 v = {0u, 0u, 0u, 0u};
        if (node < n) {
            if (q < 16) v = __ldcs((const uint4*)&hb_in[(size_t)node * 128 + q * 8]);
            else        v = __ldcs((const uint4*)&g_neighh[(size_t)node * 128 + (q - 16) * 8]);
        }
        *(uint4*)&sA[nd * ASTR + q * 8] = v;
    }
    __syncthreads();

    int wid = tid >> 5;
    int lane = tid & 31;
    int m0 = wid * 16;
    int lg = lane >> 3, lr = lane & 7;
    int a_row = m0 + lr + (lg & 1) * 8;
    int a_colb = (lg >> 1) * 8;
    int b_rowb = lr + (lg & 1) * 8;
    int b_colb = (lg >> 1) * 8;

    unsigned sA_b = smem_u32(sA);
    unsigned sW_b = smem_u32(sW);

    float acc[16][4];
    #pragma unroll
    for (int t = 0; t < 16; t++)
        #pragma unroll
        for (int c = 0; c < 4; c++) acc[t][c] = 0.f;

    #pragma unroll 1
    for (int ks = 0; ks < 16; ks++) {
        int k0 = ks * 16;
        unsigned a0, a1, a2, a3;
        ldsm_x4(a0, a1, a2, a3, sA_b + (unsigned)(a_row * ASTR + k0 + a_colb) * 2u);
        #pragma unroll
        for (int j = 0; j < 8; j++) {
            unsigned b0, b1, b2, b3;
            ldsm_x4_trans(b0, b1, b2, b3,
                          sW_b + (unsigned)((k0 + b_rowb) * WSTR + j * 16 + b_colb) * 2u);
            mma16816(acc[2 * j], a0, a1, a2, a3, b0, b1);
            mma16816(acc[2 * j + 1], a0, a1, a2, a3, b2, b3);
        }
    }

    int row0 = m0 + (lane >> 2);
    int cbase = (lane & 3) * 2;
    int node0 = base + row0;
    int node1 = node0 + 8;
    #pragma unroll
    for (int t = 0; t < 16; t++) {
        int col = t * 8 + cbase;
        float bsum0 = bs[col] + bn[col];
        float bsum1 = bs[col + 1] + bn[col + 1];
        float s0 = 0.f, s1 = 0.f, m0v = 0.f, m1v = 0.f;
        // residual base from the staged fp16 A-tile (no global read)
        float2 p0 = __half22float2(*(__half2*)&sA[row0 * ASTR + col]);
        float2 p1 = __half22float2(*(__half2*)&sA[(row0 + 8) * ASTR + col]);
        if (node0 < n) {
            float hx = p0.x + fmaxf(acc[t][0] + bsum0, 0.f);
            float hy = p0.y + fmaxf(acc[t][1] + bsum1, 0.f);
            size_t off = (size_t)node0 * 128 + col;
            if (last) __stcs((float2*)&hout[off], make_float2(hx, hy));
            else      *(__half2*)&hb_out[off] = __floats2half2_rn(hx, hy);
            s0 += hx; s1 += hy;
            m0v = fmaxf(m0v, hx); m1v = fmaxf(m1v, hy);
        }
        if (node1 < n) {
            float hx = p1.x + fmaxf(acc[t][2] + bsum0, 0.f);
            float hy = p1.y + fmaxf(acc[t][3] + bsum1, 0.f);
            size_t off = (size_t)node1 * 128 + col;
            if (last) __stcs((float2*)&hout[off], make_float2(hx, hy));
            else      *(__half2*)&hb_out[off] = __floats2half2_rn(hx, hy);
            s0 += hx; s1 += hy;
            m0v = fmaxf(m0v, hx); m1v = fmaxf(m1v, hy);
        }
        if (last) {
            #pragma unroll
            for (int o = 16; o >= 4; o >>= 1) {
                s0 += __shfl_down_sync(0xffffffffu, s0, o);
                s1 += __shfl_down_sync(0xffffffffu, s1, o);
                m0v = fmaxf(m0v, __shfl_down_sync(0xffffffffu, m0v, o));
                m1v = fmaxf(m1v, __shfl_down_sync(0xffffffffu, m1v, o));
            }
            if (lane < 4) {
                psum[wid][col] = s0;
                psum[wid][col + 1] = s1;
                pmax[wid][col] = __float_as_uint(m0v);
                pmax[wid][col + 1] = __float_as_uint(m1v);
            }
        }
    }
    if (last) {
        __syncthreads();
        if (tid < HD) {
            float s = 0.f;
            unsigned m = 0u;
            #pragma unroll
            for (int w = 0; w < 8; w++) {
                s += psum[w][tid];
                m = max(m, pmax[w][tid]);
            }
            atomicAdd(&g_gsum[tid], s);
            atomicMax(&g_gmax[tid], m);
        }
    }
}

// ---------------- final: write pooled output --------------------------------
__global__ void k_final(float* __restrict__ out, int n) {
    int t = threadIdx.x;  // 256
    if (t < 128) out[t] = g_gsum[t] / (float)n;
    else out[t] = __uint_as_float(g_gmax[t - 128]);
}

// ---------------- launch -----------------------------------------------------
extern "C" void kernel_launch(void* const* d_in, const int* in_sizes, int n_in,
                              void* d_out, int out_size) {
    const int*   mi   = (const int*)d_in[0];
    const int*   wi   = (const int*)d_in[1];
    const int*   ti   = (const int*)d_in[2];
    const float* cont = (const float*)d_in[3];
    const int*   er   = (const int*)d_in[4];
    const int*   ec   = (const int*)d_in[5];
    const float* ev   = (const float*)d_in[6];
    const float* memb = (const float*)d_in[7];
    const float* wemb = (const float*)d_in[8];
    const float* temb = (const float*)d_in[9];
    const float* W1   = (const float*)d_in[10];
    const float* b1   = (const float*)d_in[11];
    const float* W2   = (const float*)d_in[12];
    const float* b2   = (const float*)d_in[13];
    const float* Wself  = (const float*)d_in[14];
    const float* bself  = (const float*)d_in[15];
    const float* Wneigh = (const float*)d_in[16];
    const float* bneigh = (const float*)d_in[17];

    int n = in_sizes[0];
    int e = in_sizes[4];

    float* out = (float*)d_out;
    float* h = out + 256;

    cudaFuncSetAttribute(k_mlp_tc, cudaFuncAttributeMaxDynamicSharedMemorySize, SMEM_MLP_TC);
    cudaFuncSetAttribute(k_layer_tc, cudaFuncAttributeMaxDynamicSharedMemorySize, SMEM_TC);
    cudaFuncSetAttribute(k_spmm, cudaFuncAttributePreferredSharedMemoryCarveout, 0);

    int ntile = (n + 127) / 128;
    int nchunk = (n + 1023) / 1024;

    void* cnt_ptr = nullptr;
    cudaGetSymbolAddress(&cnt_ptr, g_cnt);
    __half* wlh_base = nullptr;
    cudaGetSymbolAddress((void**)&wlh_base, g_wlh);
    __half* hb0 = nullptr; __half* hb1 = nullptr;
    cudaGetSymbolAddress((void**)&hb0, g_hb);
    cudaGetSymbolAddress((void**)&hb1, g_hb2);

    // persistent side stream + events for fork-join (created once; host-side only)
    static cudaStream_t s_csr = nullptr;
    static cudaEvent_t ev_fork = nullptr, ev_join = nullptr;
    if (!s_csr) {
        cudaStreamCreateWithFlags(&s_csr, cudaStreamNonBlocking);
        cudaEventCreateWithFlags(&ev_fork, cudaEventDisableTiming);
        cudaEventCreateWithFlags(&ev_join, cudaEventDisableTiming);
    }

    // fork: CSR chain on side stream, MLP chain on main stream
    cudaEventRecord(ev_fork, 0);
    cudaStreamWaitEvent(s_csr, ev_fork, 0);

    cudaMemsetAsync(cnt_ptr, 0, (size_t)n * sizeof(int), s_csr);
    k_hist<<<(e / 4 + 255) / 256, 256, 0, s_csr>>>(er, e);
    k_scanA<<<nchunk, 256, 0, s_csr>>>(n);
    k_scanB<<<1, 256, 0, s_csr>>>(nchunk, n);
    k_scanC<<<nchunk, 256, 0, s_csr>>>(n);
    k_reorder<<<(e / 4 + 255) / 256, 256, 0, s_csr>>>(er, ec, ev, e);
    cudaEventRecord(ev_join, s_csr);

    k_prep<<<(64 * 128 + 128 * 128 + 2 * 256 * 128 + 255) / 256, 256>>>(W1, W2, Wself, Wneigh);
    k_mlp_tc<<<ntile, 256, SMEM_MLP_TC>>>(mi, wi, ti, cont, memb, wemb, temb, b1, b2, n);

    // join: spmm needs both CSR (side) and g_hb (main)
    cudaStreamWaitEvent(0, ev_join, 0);

    int hw_blocks = (int)(((long long)n * 16 + 511) / 512);

    // layer 0: hb0 -> hb1 (fp16 carry)
    k_spmm<<<hw_blocks, 512>>>(hb0, n);
    k_layer_tc<<<ntile, 256, SMEM_TC>>>(wlh_base, bself, bneigh, hb0, hb1, nullptr, n, 0);

    // layer 1: hb1 -> h (fp32 final) + fused pool
    k_spmm<<<hw_blocks, 512>>>(hb1, n);
    k_layer_tc<<<ntile, 256, SMEM_TC>>>(wlh_base + (size_t)256 * 128, bself + 128, bneigh + 128,
                                        hb1, nullptr, h, n, 1);

    k_final<<<1, 256>>>(out, n);
}